// round 14
// baseline (speedup 1.0000x reference)
#include <cuda_runtime.h>
#include <cuda_fp16.h>
#include <cstdint>
#include <math.h>

#define BATCH 128
#define DIMN  512
#define DIMW  256          // row length in half2 words
#define TE    600
#define TF    120
#define NCHUNK 5           // f2e key chunks of 128 covering 600 keys

// ---------------- scratch (device globals; no allocation allowed) ----------------
__device__ uint32_t g_Ae[BATCH * TE * DIMW];   // eeg, half2 words, pair-permuted
__device__ uint32_t g_Af[BATCH * TF * DIMW];   // fnirs, half2 words, pair-permuted
__device__ uint32_t g_Wt[6 * DIMN * DIMW];     // weights [n][k-half2], permuted
__device__ uint32_t g_Qe[BATCH * TE * DIMW];   // Q/K: half2 pair-permuted
__device__ uint32_t g_Ke[BATCH * TE * DIMW];
__device__ uint32_t g_Ve[BATCH * TE * DIMW];   // V: half2 plain
__device__ uint32_t g_Qf[BATCH * TF * DIMW];
__device__ uint32_t g_Kf[BATCH * TF * DIMW];
__device__ uint32_t g_Vf[BATCH * TF * DIMW];
__device__ float g_Opart[NCHUNK * BATCH * 128 * DIMN];
__device__ float g_M[NCHUNK * BATCH * 128];
__device__ float g_L[NCHUNK * BATCH * 128];

__device__ __forceinline__ uint32_t pack_h2(float lo, float hi) {
    half2 h = __floats2half2_rn(lo, hi);
    return *(uint32_t*)&h;
}

// m16n8k16 fp16 MMA, fp32 accumulate
__device__ __forceinline__ void mma_f16(float* c, const uint32_t* a, const uint32_t* b) {
    asm volatile("mma.sync.aligned.m16n8k16.row.col.f32.f16.f16.f32 "
        "{%0,%1,%2,%3}, {%4,%5,%6,%7}, {%8,%9}, {%0,%1,%2,%3};"
        : "+f"(c[0]), "+f"(c[1]), "+f"(c[2]), "+f"(c[3])
        : "r"(a[0]), "r"(a[1]), "r"(a[2]), "r"(a[3]), "r"(b[0]), "r"(b[1]));
}

__device__ __forceinline__ void cp_async16(uint32_t dst, const void* src) {
    asm volatile("cp.async.cg.shared.global [%0], [%1], 16;" :: "r"(dst), "l"(src));
}
#define CP_COMMIT() asm volatile("cp.async.commit_group;" ::: "memory")
#define CP_WAIT1()  asm volatile("cp.async.wait_group 1;" ::: "memory")

// ------- activation cvt: fp32 -> half2 words, pair-permuted within 8-word groups -
__global__ void cvt_perm_h(const float* __restrict__ src, uint32_t* __restrict__ dst, int n)
{
    const int i = (blockIdx.x * 256 + threadIdx.x) * 4;
    if (i < n) {
        const float4 v = *(const float4*)(src + i);
        const uint32_t w0 = pack_h2(v.x, v.y);
        const uint32_t w1 = pack_h2(v.z, v.w);
        const int p    = i >> 1;
        const int base = p & ~7;
        const int j0   = p & 7;
        const int d0 = (j0 < 4) ? 2 * j0 : 2 * (j0 - 4) + 1;
        const int j1 = j0 + 1;
        const int d1 = (j1 < 4) ? 2 * j1 : 2 * (j1 - 4) + 1;
        dst[base + d0] = w0;
        dst[base + d1] = w1;
    }
}

// ------- weight transform: W[k][n] fp32 -> Wt[n][perm(k-half2)] ------------------
__global__ void wt_h_kernel(const float* __restrict__ W, uint32_t* __restrict__ Wt)
{
    __shared__ float s[32][33];
    const int k0 = blockIdx.x * 32, n0 = blockIdx.y * 32;
    const int tx = threadIdx.x, ty = threadIdx.y;
#pragma unroll
    for (int r = ty; r < 32; r += 8)
        s[r][tx] = W[(size_t)(k0 + r) * DIMN + n0 + tx];
    __syncthreads();
#pragma unroll
    for (int w = ty; w < 16; w += 8) {
        const uint32_t h = pack_h2(s[2 * w][tx], s[2 * w + 1][tx]);
        const int j  = w & 7;
        const int jp = (j < 4) ? 2 * j : 2 * (j - 4) + 1;
        const int pos = (w & 8) + jp;
        Wt[(size_t)(n0 + tx) * DIMW + k0 / 2 + pos] = h;
    }
}

// =============== fp16 m16n8k16 projection GEMM, 128x256 tile =====================
// 8 warps (2 m x 4 n), warp tile 64x64 (4x8 frags). 3-stage cp.async.
// Stage: A 128x16 words (2048) + B 256x16 words (4096) = 6144 words.
#define GSTAGE_W  6144
#define GB_OFF_W  2048
#define GEMM_SMEM_BYTES (3 * GSTAGE_W * 4)   // 73,728

__global__ __launch_bounds__(256, 1)
void gemm_mma_kernel(const uint32_t* __restrict__ A, const uint32_t* __restrict__ Wt,
                     const float* __restrict__ b0, const float* __restrict__ b1,
                     const float* __restrict__ b2,
                     uint32_t* __restrict__ C0, uint32_t* __restrict__ C1,
                     uint32_t* __restrict__ C2)
{
    extern __shared__ uint32_t smem[];
    const uint32_t sb = (uint32_t)__cvta_generic_to_shared(smem);

    const int tid    = threadIdx.x;
    const int wid    = tid >> 5;
    const int lane   = tid & 31;
    const int warp_m = wid & 1;        // 2 warps over 128 rows
    const int warp_n = wid >> 1;       // 4 warps over 256 cols (64 each)
    const int g      = lane >> 2;
    const int t4     = lane & 3;
    const int wsel = blockIdx.x >> 1;
    const int n0   = (blockIdx.x & 1) * 256;
    const int m0   = blockIdx.y * 128;

    const uint32_t* W = Wt + (size_t)wsel * DIMN * DIMW;
    const float* bias = (wsel == 0) ? b0 : (wsel == 1) ? b1 : b2;
    uint32_t* C       = (wsel == 0) ? C0 : (wsel == 1) ? C1 : C2;

    const int sm_ = tid >> 2;          // 0..63
    const int sq  = tid & 3;           // 0..3

    float acc[4][8][4];
#pragma unroll
    for (int mt = 0; mt < 4; mt++)
#pragma unroll
        for (int nt = 0; nt < 8; nt++)
#pragma unroll
            for (int r = 0; r < 4; r++) acc[mt][nt][r] = 0.f;

    auto issue = [&](int c, int s) {
        const uint32_t stA = sb + (uint32_t)(s * GSTAGE_W) * 4;
        const uint32_t stB = sb + (uint32_t)(s * GSTAGE_W + GB_OFF_W) * 4;
#pragma unroll
        for (int i = 0; i < 2; ++i) {
            const int m = sm_ + i * 64;
            const uint32_t dstw = (uint32_t)(m * 16 + ((sq * 4) ^ ((m & 3) << 2)));
            cp_async16(stA + dstw * 4, A + (size_t)(m0 + m) * DIMW + c * 16 + sq * 4);
        }
#pragma unroll
        for (int i = 0; i < 4; ++i) {
            const int nn = sm_ + i * 64;
            const uint32_t dstw = (uint32_t)(nn * 16 + ((sq * 4) ^ ((nn & 3) << 2)));
            cp_async16(stB + dstw * 4, W + (size_t)(n0 + nn) * DIMW + c * 16 + sq * 4);
        }
        CP_COMMIT();
    };

    issue(0, 0);
    issue(1, 1);

    const int sw = (g & 3) << 2;

    for (int c = 0; c < 16; ++c) {
        const int s = c % 3;
        CP_WAIT1();
        __syncthreads();
        if (c + 2 < 16) issue(c + 2, (c + 2) % 3);

        const uint32_t* Af = smem + s * GSTAGE_W;
        const uint32_t* Bf = smem + s * GSTAGE_W + GB_OFF_W;
#pragma unroll
        for (int kk = 0; kk < 2; ++kk) {
            const int off = (kk * 8 + 2 * t4) ^ sw;
            uint32_t a[4][4], b[8][2];
#pragma unroll
            for (int mt = 0; mt < 4; ++mt) {
                const int r = warp_m * 64 + mt * 16 + g;
                const uint2 v0 = *(const uint2*)&Af[r * 16 + off];
                const uint2 v1 = *(const uint2*)&Af[(r + 8) * 16 + off];
                a[mt][0] = v0.x; a[mt][1] = v1.x; a[mt][2] = v0.y; a[mt][3] = v1.y;
            }
#pragma unroll
            for (int nt = 0; nt < 8; ++nt) {
                const int n = warp_n * 64 + nt * 8 + g;
                const uint2 vb = *(const uint2*)&Bf[n * 16 + off];
                b[nt][0] = vb.x; b[nt][1] = vb.y;
            }
#pragma unroll
            for (int mt = 0; mt < 4; ++mt)
#pragma unroll
                for (int nt = 0; nt < 8; ++nt)
                    mma_f16(acc[mt][nt], a[mt], b[nt]);
        }
    }

    // epilogue: bias add fp32, pack half2. Q/K (wsel 0,1): pair-permuted; V: plain.
#pragma unroll
    for (int mt = 0; mt < 4; ++mt) {
        const int row = m0 + warp_m * 64 + mt * 16 + g;
#pragma unroll
        for (int nt = 0; nt < 8; ++nt) {
            const int col = n0 + warp_n * 64 + nt * 8 + 2 * t4;
            const float2 bb = *(const float2*)(bias + col);
            const int wplain = n0 / 2 + warp_n * 32 + nt * 4 + t4;
            const int wperm  = n0 / 2 + warp_n * 32 + (nt >> 1) * 8 + 2 * t4 + (nt & 1);
            const int dw = (wsel == 2) ? wplain : wperm;
            C[(size_t)row * DIMW + dw] =
                pack_h2(acc[mt][nt][0] + bb.x, acc[mt][nt][1] + bb.y);
            C[(size_t)(row + 8) * DIMW + dw] =
                pack_h2(acc[mt][nt][2] + bb.x, acc[mt][nt][3] + bb.y);
        }
    }
}

// ================= fp16 attention chunk kernel (unchanged from R13) ==============
#define SS_OFF 0
#define PS_OFF 33792
#define ST_OFF 51200
#define LS_OFF 63488
#define ATTN_SMEM 63744

template <bool E2F, bool FINAL>
__global__ __launch_bounds__(256, 2)
void attn_chunk_kernel(const uint32_t* __restrict__ Q, const uint32_t* __restrict__ K,
                       const uint32_t* __restrict__ V, float* __restrict__ O,
                       float* __restrict__ Opart, float* __restrict__ Mb,
                       float* __restrict__ Lb, int Tq, int Tk)
{
    extern __shared__ char smemc[];
    float*    Ss = (float*)(smemc + SS_OFF);
    uint32_t* Ps = (uint32_t*)(smemc + PS_OFF);
    uint32_t* Qs = (uint32_t*)(smemc + ST_OFF);      // [64][16]
    uint32_t* Ks = Qs + 64 * 16;                     // [128][16]
    uint32_t* Vt = Qs;                               // [128][16] (phase-3 alias)
    float*    l_s = (float*)(smemc + LS_OFF);

    const int tid    = threadIdx.x;
    const int wid    = tid >> 5;
    const int lane   = tid & 31;
    const int warp_m = wid & 1;
    const int warp_n = wid >> 1;
    const int g      = lane >> 2;
    const int t4     = lane & 3;
    const int q0     = blockIdx.x * 64;
    const int b      = blockIdx.y;
    const int kchunk = blockIdx.z;
    const float scale = 0.044194173824159216f;
    const float NEG_INF = __int_as_float(0xff800000);
    const int sw = (g & 3) << 2;

    const uint32_t* Qb = Q + (size_t)b * Tq * DIMW;
    const uint32_t* Kb = K + (size_t)b * Tk * DIMW;
    const uint32_t* Vb = V + (size_t)b * Tk * DIMW;

    float acc[2][4][4];
#pragma unroll
    for (int mt = 0; mt < 2; mt++)
#pragma unroll
        for (int nt = 0; nt < 4; nt++)
#pragma unroll
            for (int r = 0; r < 4; r++) acc[mt][nt][r] = 0.f;

    for (int ch = 0; ch < 16; ++ch) {
        __syncthreads();
        {
            const int r = tid >> 2, c4 = tid & 3;
            uint4 v = make_uint4(0u, 0u, 0u, 0u);
            if (q0 + r < Tq)
                v = *(const uint4*)(Qb + (size_t)(q0 + r) * DIMW + ch * 16 + c4 * 4);
            *(uint4*)&Qs[r * 16 + ((c4 * 4) ^ ((r & 3) << 2))] = v;
        }
#pragma unroll
        for (int i = 0; i < 2; ++i) {
            const int lin = i * 256 + tid;
            const int r = lin >> 2, c4 = lin & 3;
            const int key = kchunk * 128 + r;
            uint4 v = make_uint4(0u, 0u, 0u, 0u);
            if (key < Tk)
                v = *(const uint4*)(Kb + (size_t)key * DIMW + ch * 16 + c4 * 4);
            *(uint4*)&Ks[r * 16 + ((c4 * 4) ^ ((r & 3) << 2))] = v;
        }
        __syncthreads();
#pragma unroll
        for (int kk = 0; kk < 2; ++kk) {
            const int off = (kk * 8 + 2 * t4) ^ sw;
            uint32_t a[2][4], bb[4][2];
#pragma unroll
            for (int mt = 0; mt < 2; ++mt) {
                const int r = warp_m * 32 + mt * 16 + g;
                const uint2 v0 = *(const uint2*)&Qs[r * 16 + off];
                const uint2 v1 = *(const uint2*)&Qs[(r + 8) * 16 + off];
                a[mt][0] = v0.x; a[mt][1] = v1.x; a[mt][2] = v0.y; a[mt][3] = v1.y;
            }
#pragma unroll
            for (int nt = 0; nt < 4; ++nt) {
                const int n = warp_n * 32 + nt * 8 + g;
                const uint2 vb = *(const uint2*)&Ks[n * 16 + off];
                bb[nt][0] = vb.x; bb[nt][1] = vb.y;
            }
#pragma unroll
            for (int mt = 0; mt < 2; ++mt)
#pragma unroll
                for (int nt = 0; nt < 4; ++nt)
                    mma_f16(acc[mt][nt], a[mt], bb[nt]);
        }
    }
#pragma unroll
    for (int mt = 0; mt < 2; ++mt) {
#pragma unroll
        for (int half = 0; half < 2; ++half) {
            const int row = warp_m * 32 + mt * 16 + half * 8 + g;
            const int q   = q0 + row;
            const int j0g = q / 20;
#pragma unroll
            for (int nt = 0; nt < 4; ++nt) {
                const int colc = warp_n * 32 + nt * 8 + 2 * t4;
                float vout[2];
#pragma unroll
                for (int e = 0; e < 2; ++e) {
                    const int key = kchunk * 128 + colc + e;
                    float val;
                    if (key >= Tk) val = NEG_INF;
                    else {
                        bool valid;
                        if (E2F) valid = (key >= j0g + 20) && (key <= j0g + 80);
                        else { const int gg = key / 20; valid = (q >= gg + 20) && (q <= gg + 80); }
                        val = valid ? acc[mt][nt][half * 2 + e] * scale : -1e9f;
                    }
                    vout[e] = val;
                }
                *(float2*)&Ss[row * 132 + colc] = make_float2(vout[0], vout[1]);
            }
        }
    }
    __syncthreads();

    {
        const int row  = tid >> 2;
        const int part = tid & 3;
        const float* srow = Ss + row * 132;

        float mx = NEG_INF;
#pragma unroll
        for (int i = 0; i < 16; ++i) {
            const float2 s2 = *(const float2*)&srow[2 * (part + 4 * i)];
            mx = fmaxf(mx, fmaxf(s2.x, s2.y));
        }
        mx = fmaxf(mx, __shfl_xor_sync(0xffffffffu, mx, 1));
        mx = fmaxf(mx, __shfl_xor_sync(0xffffffffu, mx, 2));
        float sum = 0.f;
        uint32_t* prow = Ps + row * 68;
#pragma unroll
        for (int i = 0; i < 16; ++i) {
            const int w = part + 4 * i;
            const float2 s2 = *(const float2*)&srow[2 * w];
            const float e0 = __expf(s2.x - mx);
            const float e1 = __expf(s2.y - mx);
            sum += e0 + e1;
            const int j = w & 7;
            const int pw = (w & ~7) + ((j < 4) ? 2 * j : 2 * (j - 4) + 1);
            prow[pw] = pack_h2(e0, e1);
        }
        sum += __shfl_xor_sync(0xffffffffu, sum, 1);
        sum += __shfl_xor_sync(0xffffffffu, sum, 2);
        if (part == 0) {
            l_s[row] = sum;
            if (!FINAL) {
                const int idx = (kchunk * BATCH + b) * 128 + q0 + row;
                Mb[idx] = mx;
                Lb[idx] = sum;
            }
        }
    }
    __syncthreads();

    for (int nc = 0; nc < 4; ++nc) {
        float oacc[2][4][4];
#pragma unroll
        for (int mt = 0; mt < 2; mt++)
#pragma unroll
            for (int nt = 0; nt < 4; nt++)
#pragma unroll
                for (int r = 0; r < 4; r++) oacc[mt][nt][r] = 0.f;

        for (int ks = 0; ks < 4; ++ks) {
            __syncthreads();
#pragma unroll
            for (int i = 0; i < 4; ++i) {
                const int u  = i * 256 + tid;
                const int kw = (u >> 2) & 15;
                const int wd = (u & 3) | ((u >> 6) << 2);
                const int key0 = kchunk * 128 + ks * 32 + 2 * kw;
                uint32_t w0 = 0u, w1 = 0u;
                if (key0 < Tk)     w0 = Vb[(size_t)key0 * DIMW + nc * 64 + wd];
                if (key0 + 1 < Tk) w1 = Vb[(size_t)(key0 + 1) * DIMW + nc * 64 + wd];
                const uint32_t lo = __byte_perm(w0, w1, 0x5410);
                const uint32_t hi = __byte_perm(w0, w1, 0x7632);
                const int j  = kw & 7;
                const int ps = (kw & 8) + ((j < 4) ? 2 * j : 2 * (j - 4) + 1);
                const int d0 = 2 * wd, d1 = 2 * wd + 1;
                Vt[d0 * 16 + (ps ^ ((d0 & 3) << 2))] = lo;
                Vt[d1 * 16 + (ps ^ ((d1 & 3) << 2))] = hi;
            }
            __syncthreads();
#pragma unroll
            for (int kk = 0; kk < 2; ++kk) {
                const int offv = (kk * 8 + 2 * t4) ^ sw;
                const int offp = ks * 16 + kk * 8 + 2 * t4;
                uint32_t a[2][4], bb[4][2];
#pragma unroll
                for (int mt = 0; mt < 2; ++mt) {
                    const int r = warp_m * 32 + mt * 16 + g;
                    const uint2 v0 = *(const uint2*)&Ps[r * 68 + offp];
                    const uint2 v1 = *(const uint2*)&Ps[(r + 8) * 68 + offp];
                    a[mt][0] = v0.x; a[mt][1] = v1.x; a[mt][2] = v0.y; a[mt][3] = v1.y;
                }
#pragma unroll
                for (int nt = 0; nt < 4; ++nt) {
                    const int n = warp_n * 32 + nt * 8 + g;
                    const uint2 vb = *(const uint2*)&Vt[n * 16 + offv];
                    bb[nt][0] = vb.x; bb[nt][1] = vb.y;
                }
#pragma unroll
                for (int mt = 0; mt < 2; ++mt)
#pragma unroll
                    for (int nt = 0; nt < 4; ++nt)
                        mma_f16(oacc[mt][nt], a[mt], bb[nt]);
            }
        }
#pragma unroll
        for (int mt = 0; mt < 2; ++mt) {
#pragma unroll
            for (int half = 0; half < 2; ++half) {
                const int row = warp_m * 32 + mt * 16 + half * 8 + g;
                const int q   = q0 + row;
#pragma unroll
                for (int nt = 0; nt < 4; ++nt) {
                    const int col = nc * 128 + warp_n * 32 + nt * 8 + 2 * t4;
                    const float v0 = oacc[mt][nt][half * 2 + 0];
                    const float v1 = oacc[mt][nt][half * 2 + 1];
                    if (FINAL) {
                        if (q < Tq) {
                            const float inv = 1.f / l_s[row];
                            *(float2*)(O + ((size_t)b * Tq + q) * DIMN + col) =
                                make_float2(v0 * inv, v1 * inv);
                        }
                    } else {
                        float* dst = Opart + (((size_t)kchunk * BATCH + b) * 128 + q) * DIMN + col;
                        *(float2*)dst = make_float2(v0, v1);
                    }
                }
            }
        }
    }
}

// ----------------- f2e combine: merge 5 chunk partials per row -------------------
__global__ void combine_f2e(const float* __restrict__ Opart,
                            const float* __restrict__ Mb, const float* __restrict__ Lb,
                            float* __restrict__ O)
{
    const int q = blockIdx.x;
    const int b = blockIdx.y;
    const int t = threadIdx.x;
    float m[NCHUNK], w[NCHUNK];
    float M = __int_as_float(0xff800000);
#pragma unroll
    for (int c = 0; c < NCHUNK; ++c) {
        m[c] = Mb[(c * BATCH + b) * 128 + q];
        M = fmaxf(M, m[c]);
    }
    float den = 0.f;
#pragma unroll
    for (int c = 0; c < NCHUNK; ++c) {
        w[c] = __expf(m[c] - M);
        den += w[c] * Lb[(c * BATCH + b) * 128 + q];
    }
    const float inv = 1.f / den;
    float4 o = make_float4(0.f, 0.f, 0.f, 0.f);
#pragma unroll
    for (int c = 0; c < NCHUNK; ++c) {
        const float4 p = *(const float4*)(Opart + (((size_t)c * BATCH + b) * 128 + q) * DIMN + t * 4);
        const float s = w[c] * inv;
        o.x += s * p.x; o.y += s * p.y; o.z += s * p.z; o.w += s * p.w;
    }
    *(float4*)(O + ((size_t)b * TF + q) * DIMN + t * 4) = o;
}

extern "C" void kernel_launch(void* const* d_in, const int* in_sizes, int n_in,
                              void* d_out, int out_size)
{
    (void)in_sizes; (void)n_in; (void)out_size;

    const float* eeg   = (const float*)d_in[0];
    const float* fnirs = (const float*)d_in[1];
    const float* Wqe = (const float*)d_in[2];
    const float* bqe = (const float*)d_in[3];
    const float* Wke = (const float*)d_in[4];
    const float* bke = (const float*)d_in[5];
    const float* Wve = (const float*)d_in[6];
    const float* bve = (const float*)d_in[7];
    const float* Wqf = (const float*)d_in[8];
    const float* bqf = (const float*)d_in[9];
    const float* Wkf = (const float*)d_in[10];
    const float* bkf = (const float*)d_in[11];
    const float* Wvf = (const float*)d_in[12];
    const float* bvf = (const float*)d_in[13];

    uint32_t *Ae, *Af, *Wt, *Qe, *Ke, *Ve, *Qf, *Kf, *Vf;
    float *Opart, *Mb, *Lb;
    cudaGetSymbolAddress((void**)&Ae, g_Ae);
    cudaGetSymbolAddress((void**)&Af, g_Af);
    cudaGetSymbolAddress((void**)&Wt, g_Wt);
    cudaGetSymbolAddress((void**)&Qe, g_Qe);
    cudaGetSymbolAddress((void**)&Ke, g_Ke);
    cudaGetSymbolAddress((void**)&Ve, g_Ve);
    cudaGetSymbolAddress((void**)&Qf, g_Qf);
    cudaGetSymbolAddress((void**)&Kf, g_Kf);
    cudaGetSymbolAddress((void**)&Vf, g_Vf);
    cudaGetSymbolAddress((void**)&Opart, g_Opart);
    cudaGetSymbolAddress((void**)&Mb, g_M);
    cudaGetSymbolAddress((void**)&Lb, g_L);

    float* out           = (float*)d_out;
    float* aligned_eeg   = out;                                // [B, TF, D]
    float* aligned_fnirs = out + (size_t)BATCH * TF * DIMN;    // [B, TE, D]

    const int Me = BATCH * TE;
    const int Mf = BATCH * TF;
    const size_t NWW = (size_t)DIMN * DIMW;

    const int ne = Me * DIMN, nf = Mf * DIMN;
    cvt_perm_h<<<(ne / 4 + 255) / 256, 256>>>(eeg,   Ae, ne);
    cvt_perm_h<<<(nf / 4 + 255) / 256, 256>>>(fnirs, Af, nf);
    dim3 wblk(32, 8), wgrd(DIMN / 32, DIMN / 32);
    wt_h_kernel<<<wgrd, wblk>>>(Wqe, Wt + 0 * NWW);
    wt_h_kernel<<<wgrd, wblk>>>(Wke, Wt + 1 * NWW);
    wt_h_kernel<<<wgrd, wblk>>>(Wve, Wt + 2 * NWW);
    wt_h_kernel<<<wgrd, wblk>>>(Wqf, Wt + 3 * NWW);
    wt_h_kernel<<<wgrd, wblk>>>(Wkf, Wt + 4 * NWW);
    wt_h_kernel<<<wgrd, wblk>>>(Wvf, Wt + 5 * NWW);

    cudaFuncSetAttribute(gemm_mma_kernel,
                         cudaFuncAttributeMaxDynamicSharedMemorySize, GEMM_SMEM_BYTES);

    dim3 blk(256);
    gemm_mma_kernel<<<dim3(6, Me / 128), blk, GEMM_SMEM_BYTES>>>(
        Ae, Wt, bqe, bke, bve, Qe, Ke, Ve);
    gemm_mma_kernel<<<dim3(6, Mf / 128), blk, GEMM_SMEM_BYTES>>>(
        Af, Wt + 3 * NWW, bqf, bkf, bvf, Qf, Kf, Vf);

    cudaFuncSetAttribute((const void*)attn_chunk_kernel<true, true>,
                         cudaFuncAttributeMaxDynamicSharedMemorySize, ATTN_SMEM);
    cudaFuncSetAttribute((const void*)attn_chunk_kernel<false, false>,
                         cudaFuncAttributeMaxDynamicSharedMemorySize, ATTN_SMEM);

    attn_chunk_kernel<true, true><<<dim3(10, BATCH, 1), blk, ATTN_SMEM>>>(
        Qe, Kf, Vf, aligned_fnirs, nullptr, nullptr, nullptr, TE, TF);
    attn_chunk_kernel<false, false><<<dim3(2, BATCH, NCHUNK), blk, ATTN_SMEM>>>(
        Qf, Ke, Ve, nullptr, Opart, Mb, Lb, TF, TE);
    combine_f2e<<<dim3(TF, BATCH), dim3(128)>>>(Opart, Mb, Lb, aligned_eeg);
}

// round 15
// speedup vs baseline: 1.0775x; 1.0775x over previous
#include <cuda_runtime.h>
#include <cuda_fp16.h>
#include <cstdint>
#include <math.h>

#define BATCH 128
#define DIMN  512
#define DIMW  256          // row length in half2 words
#define TE    600
#define TF    120
#define NCHUNK 5           // f2e key chunks of 128 covering 600 keys

// ---------------- scratch (device globals; no allocation allowed) ----------------
__device__ uint32_t g_Ae[BATCH * TE * DIMW];   // eeg, half2 words, pair-permuted
__device__ uint32_t g_Af[BATCH * TF * DIMW];   // fnirs, half2 words, pair-permuted
__device__ uint32_t g_Wt[6 * DIMN * DIMW];     // weights [n][k-half2], permuted
__device__ uint32_t g_Qe[BATCH * TE * DIMW];   // Q/K: half2 pair-permuted
__device__ uint32_t g_Ke[BATCH * TE * DIMW];
__device__ uint32_t g_Ve[BATCH * TE * DIMW];   // V: half2 plain
__device__ uint32_t g_Qf[BATCH * TF * DIMW];
__device__ uint32_t g_Kf[BATCH * TF * DIMW];
__device__ uint32_t g_Vf[BATCH * TF * DIMW];
__device__ uint32_t g_OpartH[NCHUNK * BATCH * 128 * DIMW];  // f2e partial O, half2
__device__ float g_M[NCHUNK * BATCH * 128];
__device__ float g_L[NCHUNK * BATCH * 128];

__device__ __forceinline__ uint32_t pack_h2(float lo, float hi) {
    half2 h = __floats2half2_rn(lo, hi);
    return *(uint32_t*)&h;
}

// m16n8k16 fp16 MMA, fp32 accumulate
__device__ __forceinline__ void mma_f16(float* c, const uint32_t* a, const uint32_t* b) {
    asm volatile("mma.sync.aligned.m16n8k16.row.col.f32.f16.f16.f32 "
        "{%0,%1,%2,%3}, {%4,%5,%6,%7}, {%8,%9}, {%0,%1,%2,%3};"
        : "+f"(c[0]), "+f"(c[1]), "+f"(c[2]), "+f"(c[3])
        : "r"(a[0]), "r"(a[1]), "r"(a[2]), "r"(a[3]), "r"(b[0]), "r"(b[1]));
}

__device__ __forceinline__ void cp_async16(uint32_t dst, const void* src) {
    asm volatile("cp.async.cg.shared.global [%0], [%1], 16;" :: "r"(dst), "l"(src));
}
#define CP_COMMIT() asm volatile("cp.async.commit_group;" ::: "memory")
#define CP_WAIT1()  asm volatile("cp.async.wait_group 1;" ::: "memory")

// ------- activation cvt: fp32 -> half2 words, pair-permuted within 8-word groups -
__global__ void cvt_perm_h(const float* __restrict__ src, uint32_t* __restrict__ dst, int n)
{
    const int i = (blockIdx.x * 256 + threadIdx.x) * 4;
    if (i < n) {
        const float4 v = *(const float4*)(src + i);
        const uint32_t w0 = pack_h2(v.x, v.y);
        const uint32_t w1 = pack_h2(v.z, v.w);
        const int p    = i >> 1;
        const int base = p & ~7;
        const int j0   = p & 7;
        const int d0 = (j0 < 4) ? 2 * j0 : 2 * (j0 - 4) + 1;
        const int j1 = j0 + 1;
        const int d1 = (j1 < 4) ? 2 * j1 : 2 * (j1 - 4) + 1;
        dst[base + d0] = w0;
        dst[base + d1] = w1;
    }
}

// ------- weight transform (all 6 matrices in one launch; z selects) --------------
__global__ void wt_h_kernel(const float* __restrict__ W0, const float* __restrict__ W1,
                            const float* __restrict__ W2, const float* __restrict__ W3,
                            const float* __restrict__ W4, const float* __restrict__ W5,
                            uint32_t* __restrict__ Wt)
{
    __shared__ float s[32][33];
    const int k0 = blockIdx.x * 32, n0 = blockIdx.y * 32;
    const int z  = blockIdx.z;
    const float* W = (z == 0) ? W0 : (z == 1) ? W1 : (z == 2) ? W2
                   : (z == 3) ? W3 : (z == 4) ? W4 : W5;
    uint32_t* Wd = Wt + (size_t)z * DIMN * DIMW;
    const int tx = threadIdx.x, ty = threadIdx.y;
#pragma unroll
    for (int r = ty; r < 32; r += 8)
        s[r][tx] = W[(size_t)(k0 + r) * DIMN + n0 + tx];
    __syncthreads();
#pragma unroll
    for (int w = ty; w < 16; w += 8) {
        const uint32_t h = pack_h2(s[2 * w][tx], s[2 * w + 1][tx]);
        const int j  = w & 7;
        const int jp = (j < 4) ? 2 * j : 2 * (j - 4) + 1;
        const int pos = (w & 8) + jp;
        Wd[(size_t)(n0 + tx) * DIMW + k0 / 2 + pos] = h;
    }
}

// =============== fp16 m16n8k16 projection GEMM (R13 config: 128x128, 2 CTA/SM) ===
#define GSTAGE_W  4096
#define GB_OFF_W  2048
#define GEMM_SMEM_BYTES (3 * GSTAGE_W * 4)

__global__ __launch_bounds__(256, 2)
void gemm_mma_kernel(const uint32_t* __restrict__ A, const uint32_t* __restrict__ Wt,
                     const float* __restrict__ b0, const float* __restrict__ b1,
                     const float* __restrict__ b2,
                     uint32_t* __restrict__ C0, uint32_t* __restrict__ C1,
                     uint32_t* __restrict__ C2)
{
    extern __shared__ uint32_t smem[];
    const uint32_t sb = (uint32_t)__cvta_generic_to_shared(smem);

    const int tid    = threadIdx.x;
    const int wid    = tid >> 5;
    const int lane   = tid & 31;
    const int warp_m = wid & 1;
    const int warp_n = wid >> 1;
    const int g      = lane >> 2;
    const int t4     = lane & 3;
    const int wsel = blockIdx.x >> 2;
    const int n0   = (blockIdx.x & 3) * 128;
    const int m0   = blockIdx.y * 128;

    const uint32_t* W = Wt + (size_t)wsel * DIMN * DIMW;
    const float* bias = (wsel == 0) ? b0 : (wsel == 1) ? b1 : b2;
    uint32_t* C       = (wsel == 0) ? C0 : (wsel == 1) ? C1 : C2;

    const int sm_ = tid >> 2;
    const int sq  = tid & 3;

    float acc[4][4][4];
#pragma unroll
    for (int mt = 0; mt < 4; mt++)
#pragma unroll
        for (int nt = 0; nt < 4; nt++)
#pragma unroll
            for (int r = 0; r < 4; r++) acc[mt][nt][r] = 0.f;

    auto issue = [&](int c, int s) {
        const uint32_t stA = sb + (uint32_t)(s * GSTAGE_W) * 4;
        const uint32_t stB = sb + (uint32_t)(s * GSTAGE_W + GB_OFF_W) * 4;
#pragma unroll
        for (int i = 0; i < 2; ++i) {
            const int m = sm_ + i * 64;
            const uint32_t dstw = (uint32_t)(m * 16 + ((sq * 4) ^ ((m & 3) << 2)));
            cp_async16(stA + dstw * 4, A + (size_t)(m0 + m) * DIMW + c * 16 + sq * 4);
        }
#pragma unroll
        for (int i = 0; i < 2; ++i) {
            const int nn = sm_ + i * 64;
            const uint32_t dstw = (uint32_t)(nn * 16 + ((sq * 4) ^ ((nn & 3) << 2)));
            cp_async16(stB + dstw * 4, W + (size_t)(n0 + nn) * DIMW + c * 16 + sq * 4);
        }
        CP_COMMIT();
    };

    issue(0, 0);
    issue(1, 1);

    const int sw = (g & 3) << 2;

    for (int c = 0; c < 16; ++c) {
        const int s = c % 3;
        CP_WAIT1();
        __syncthreads();
        if (c + 2 < 16) issue(c + 2, (c + 2) % 3);

        const uint32_t* Af = smem + s * GSTAGE_W;
        const uint32_t* Bf = smem + s * GSTAGE_W + GB_OFF_W;
#pragma unroll
        for (int kk = 0; kk < 2; ++kk) {
            const int off = (kk * 8 + 2 * t4) ^ sw;
            uint32_t a[4][4], b[4][2];
#pragma unroll
            for (int mt = 0; mt < 4; ++mt) {
                const int r = warp_m * 64 + mt * 16 + g;
                const uint2 v0 = *(const uint2*)&Af[r * 16 + off];
                const uint2 v1 = *(const uint2*)&Af[(r + 8) * 16 + off];
                a[mt][0] = v0.x; a[mt][1] = v1.x; a[mt][2] = v0.y; a[mt][3] = v1.y;
            }
#pragma unroll
            for (int nt = 0; nt < 4; ++nt) {
                const int n = warp_n * 32 + nt * 8 + g;
                const uint2 vb = *(const uint2*)&Bf[n * 16 + off];
                b[nt][0] = vb.x; b[nt][1] = vb.y;
            }
#pragma unroll
            for (int mt = 0; mt < 4; ++mt)
#pragma unroll
                for (int nt = 0; nt < 4; ++nt)
                    mma_f16(acc[mt][nt], a[mt], b[nt]);
        }
    }

    // epilogue: bias add fp32, pack half2. Q/K (wsel 0,1): pair-permuted; V: plain.
#pragma unroll
    for (int mt = 0; mt < 4; ++mt) {
        const int row = m0 + warp_m * 64 + mt * 16 + g;
#pragma unroll
        for (int nt = 0; nt < 4; ++nt) {
            const int col = n0 + warp_n * 32 + nt * 8 + 2 * t4;
            const float2 bb = *(const float2*)(bias + col);
            const int wplain = n0 / 2 + warp_n * 16 + nt * 4 + t4;
            const int wperm  = n0 / 2 + warp_n * 16 + ((nt & 2) ? 8 : 0) + 2 * t4 + (nt & 1);
            const int dw = (wsel == 2) ? wplain : wperm;
            C[(size_t)row * DIMW + dw] =
                pack_h2(acc[mt][nt][0] + bb.x, acc[mt][nt][1] + bb.y);
            C[(size_t)(row + 8) * DIMW + dw] =
                pack_h2(acc[mt][nt][2] + bb.x, acc[mt][nt][3] + bb.y);
        }
    }
}

// ================= fp16 attention chunk kernel ===================================
#define SS_OFF 0
#define PS_OFF 33792
#define ST_OFF 51200
#define LS_OFF 63488
#define ATTN_SMEM 63744

template <bool E2F, bool FINAL>
__global__ __launch_bounds__(256, 2)
void attn_chunk_kernel(const uint32_t* __restrict__ Q, const uint32_t* __restrict__ K,
                       const uint32_t* __restrict__ V, float* __restrict__ O,
                       uint32_t* __restrict__ OpartH, float* __restrict__ Mb,
                       float* __restrict__ Lb, int Tq, int Tk)
{
    extern __shared__ char smemc[];
    float*    Ss = (float*)(smemc + SS_OFF);
    uint32_t* Ps = (uint32_t*)(smemc + PS_OFF);
    uint32_t* Qs = (uint32_t*)(smemc + ST_OFF);      // [64][16]
    uint32_t* Ks = Qs + 64 * 16;                     // [128][16]
    uint32_t* Vt = Qs;                               // [128][16] (phase-3 alias)
    float*    l_s = (float*)(smemc + LS_OFF);

    const int tid    = threadIdx.x;
    const int wid    = tid >> 5;
    const int lane   = tid & 31;
    const int warp_m = wid & 1;
    const int warp_n = wid >> 1;
    const int g      = lane >> 2;
    const int t4     = lane & 3;
    const int q0     = blockIdx.x * 64;
    const int b      = blockIdx.y;
    const int kchunk = blockIdx.z;
    const float scale = 0.044194173824159216f;
    const float NEG_INF = __int_as_float(0xff800000);
    const int sw = (g & 3) << 2;

    const uint32_t* Qb = Q + (size_t)b * Tq * DIMW;
    const uint32_t* Kb = K + (size_t)b * Tk * DIMW;
    const uint32_t* Vb = V + (size_t)b * Tk * DIMW;

    float acc[2][4][4];
#pragma unroll
    for (int mt = 0; mt < 2; mt++)
#pragma unroll
        for (int nt = 0; nt < 4; nt++)
#pragma unroll
            for (int r = 0; r < 4; r++) acc[mt][nt][r] = 0.f;

    for (int ch = 0; ch < 16; ++ch) {
        __syncthreads();
        {
            const int r = tid >> 2, c4 = tid & 3;
            uint4 v = make_uint4(0u, 0u, 0u, 0u);
            if (q0 + r < Tq)
                v = *(const uint4*)(Qb + (size_t)(q0 + r) * DIMW + ch * 16 + c4 * 4);
            *(uint4*)&Qs[r * 16 + ((c4 * 4) ^ ((r & 3) << 2))] = v;
        }
#pragma unroll
        for (int i = 0; i < 2; ++i) {
            const int lin = i * 256 + tid;
            const int r = lin >> 2, c4 = lin & 3;
            const int key = kchunk * 128 + r;
            uint4 v = make_uint4(0u, 0u, 0u, 0u);
            if (key < Tk)
                v = *(const uint4*)(Kb + (size_t)key * DIMW + ch * 16 + c4 * 4);
            *(uint4*)&Ks[r * 16 + ((c4 * 4) ^ ((r & 3) << 2))] = v;
        }
        __syncthreads();
#pragma unroll
        for (int kk = 0; kk < 2; ++kk) {
            const int off = (kk * 8 + 2 * t4) ^ sw;
            uint32_t a[2][4], bb[4][2];
#pragma unroll
            for (int mt = 0; mt < 2; ++mt) {
                const int r = warp_m * 32 + mt * 16 + g;
                const uint2 v0 = *(const uint2*)&Qs[r * 16 + off];
                const uint2 v1 = *(const uint2*)&Qs[(r + 8) * 16 + off];
                a[mt][0] = v0.x; a[mt][1] = v1.x; a[mt][2] = v0.y; a[mt][3] = v1.y;
            }
#pragma unroll
            for (int nt = 0; nt < 4; ++nt) {
                const int n = warp_n * 32 + nt * 8 + g;
                const uint2 vb = *(const uint2*)&Ks[n * 16 + off];
                bb[nt][0] = vb.x; bb[nt][1] = vb.y;
            }
#pragma unroll
            for (int mt = 0; mt < 2; ++mt)
#pragma unroll
                for (int nt = 0; nt < 4; ++nt)
                    mma_f16(acc[mt][nt], a[mt], bb[nt]);
        }
    }
#pragma unroll
    for (int mt = 0; mt < 2; ++mt) {
#pragma unroll
        for (int half = 0; half < 2; ++half) {
            const int row = warp_m * 32 + mt * 16 + half * 8 + g;
            const int q   = q0 + row;
            const int j0g = q / 20;
#pragma unroll
            for (int nt = 0; nt < 4; ++nt) {
                const int colc = warp_n * 32 + nt * 8 + 2 * t4;
                float vout[2];
#pragma unroll
                for (int e = 0; e < 2; ++e) {
                    const int key = kchunk * 128 + colc + e;
                    float val;
                    if (key >= Tk) val = NEG_INF;
                    else {
                        bool valid;
                        if (E2F) valid = (key >= j0g + 20) && (key <= j0g + 80);
                        else { const int gg = key / 20; valid = (q >= gg + 20) && (q <= gg + 80); }
                        val = valid ? acc[mt][nt][half * 2 + e] * scale : -1e9f;
                    }
                    vout[e] = val;
                }
                *(float2*)&Ss[row * 132 + colc] = make_float2(vout[0], vout[1]);
            }
        }
    }
    __syncthreads();

    {
        const int row  = tid >> 2;
        const int part = tid & 3;
        const float* srow = Ss + row * 132;

        float mx = NEG_INF;
#pragma unroll
        for (int i = 0; i < 16; ++i) {
            const float2 s2 = *(const float2*)&srow[2 * (part + 4 * i)];
            mx = fmaxf(mx, fmaxf(s2.x, s2.y));
        }
        mx = fmaxf(mx, __shfl_xor_sync(0xffffffffu, mx, 1));
        mx = fmaxf(mx, __shfl_xor_sync(0xffffffffu, mx, 2));
        float sum = 0.f;
        uint32_t* prow = Ps + row * 68;
#pragma unroll
        for (int i = 0; i < 16; ++i) {
            const int w = part + 4 * i;
            const float2 s2 = *(const float2*)&srow[2 * w];
            const float e0 = __expf(s2.x - mx);
            const float e1 = __expf(s2.y - mx);
            sum += e0 + e1;
            const int j = w & 7;
            const int pw = (w & ~7) + ((j < 4) ? 2 * j : 2 * (j - 4) + 1);
            prow[pw] = pack_h2(e0, e1);
        }
        sum += __shfl_xor_sync(0xffffffffu, sum, 1);
        sum += __shfl_xor_sync(0xffffffffu, sum, 2);
        if (part == 0) {
            l_s[row] = sum;
            if (!FINAL) {
                const int idx = (kchunk * BATCH + b) * 128 + q0 + row;
                Mb[idx] = mx;
                Lb[idx] = sum;
            }
        }
    }
    __syncthreads();

    for (int nc = 0; nc < 4; ++nc) {
        float oacc[2][4][4];
#pragma unroll
        for (int mt = 0; mt < 2; mt++)
#pragma unroll
            for (int nt = 0; nt < 4; nt++)
#pragma unroll
                for (int r = 0; r < 4; r++) oacc[mt][nt][r] = 0.f;

        for (int ks = 0; ks < 4; ++ks) {
            __syncthreads();
#pragma unroll
            for (int i = 0; i < 4; ++i) {
                const int u  = i * 256 + tid;
                const int kw = (u >> 2) & 15;
                const int wd = (u & 3) | ((u >> 6) << 2);
                const int key0 = kchunk * 128 + ks * 32 + 2 * kw;
                uint32_t w0 = 0u, w1 = 0u;
                if (key0 < Tk)     w0 = Vb[(size_t)key0 * DIMW + nc * 64 + wd];
                if (key0 + 1 < Tk) w1 = Vb[(size_t)(key0 + 1) * DIMW + nc * 64 + wd];
                const uint32_t lo = __byte_perm(w0, w1, 0x5410);
                const uint32_t hi = __byte_perm(w0, w1, 0x7632);
                const int j  = kw & 7;
                const int ps = (kw & 8) + ((j < 4) ? 2 * j : 2 * (j - 4) + 1);
                const int d0 = 2 * wd, d1 = 2 * wd + 1;
                Vt[d0 * 16 + (ps ^ ((d0 & 3) << 2))] = lo;
                Vt[d1 * 16 + (ps ^ ((d1 & 3) << 2))] = hi;
            }
            __syncthreads();
#pragma unroll
            for (int kk = 0; kk < 2; ++kk) {
                const int offv = (kk * 8 + 2 * t4) ^ sw;
                const int offp = ks * 16 + kk * 8 + 2 * t4;
                uint32_t a[2][4], bb[4][2];
#pragma unroll
                for (int mt = 0; mt < 2; ++mt) {
                    const int r = warp_m * 32 + mt * 16 + g;
                    const uint2 v0 = *(const uint2*)&Ps[r * 68 + offp];
                    const uint2 v1 = *(const uint2*)&Ps[(r + 8) * 68 + offp];
                    a[mt][0] = v0.x; a[mt][1] = v1.x; a[mt][2] = v0.y; a[mt][3] = v1.y;
                }
#pragma unroll
                for (int nt = 0; nt < 4; ++nt) {
                    const int n = warp_n * 32 + nt * 8 + g;
                    const uint2 vb = *(const uint2*)&Vt[n * 16 + offv];
                    bb[nt][0] = vb.x; bb[nt][1] = vb.y;
                }
#pragma unroll
                for (int mt = 0; mt < 2; ++mt)
#pragma unroll
                    for (int nt = 0; nt < 4; ++nt)
                        mma_f16(oacc[mt][nt], a[mt], bb[nt]);
            }
        }
#pragma unroll
        for (int mt = 0; mt < 2; ++mt) {
#pragma unroll
            for (int half = 0; half < 2; ++half) {
                const int row = warp_m * 32 + mt * 16 + half * 8 + g;
                const int q   = q0 + row;
#pragma unroll
                for (int nt = 0; nt < 4; ++nt) {
                    const int col = nc * 128 + warp_n * 32 + nt * 8 + 2 * t4;
                    const float v0 = oacc[mt][nt][half * 2 + 0];
                    const float v1 = oacc[mt][nt][half * 2 + 1];
                    if (FINAL) {
                        if (q < Tq) {
                            const float inv = 1.f / l_s[row];
                            *(float2*)(O + ((size_t)b * Tq + q) * DIMN + col) =
                                make_float2(v0 * inv, v1 * inv);
                        }
                    } else {
                        OpartH[(((size_t)kchunk * BATCH + b) * 128 + q) * DIMW + col / 2] =
                            pack_h2(v0, v1);
                    }
                }
            }
        }
    }
}

// ----------------- f2e combine: merge 5 fp16 chunk partials per row --------------
__global__ void combine_f2e(const uint32_t* __restrict__ OpartH,
                            const float* __restrict__ Mb, const float* __restrict__ Lb,
                            float* __restrict__ O)
{
    const int q = blockIdx.x;
    const int b = blockIdx.y;
    const int t = threadIdx.x;
    float m[NCHUNK], w[NCHUNK];
    float M = __int_as_float(0xff800000);
#pragma unroll
    for (int c = 0; c < NCHUNK; ++c) {
        m[c] = Mb[(c * BATCH + b) * 128 + q];
        M = fmaxf(M, m[c]);
    }
    float den = 0.f;
#pragma unroll
    for (int c = 0; c < NCHUNK; ++c) {
        w[c] = __expf(m[c] - M);
        den += w[c] * Lb[(c * BATCH + b) * 128 + q];
    }
    const float inv = 1.f / den;
    float4 o = make_float4(0.f, 0.f, 0.f, 0.f);
#pragma unroll
    for (int c = 0; c < NCHUNK; ++c) {
        const uint2 p2 = *(const uint2*)(OpartH + (((size_t)c * BATCH + b) * 128 + q) * DIMW + t * 2);
        const half2 h0 = *(const half2*)&p2.x;
        const half2 h1 = *(const half2*)&p2.y;
        const float s = w[c] * inv;
        o.x += s * __low2float(h0);  o.y += s * __high2float(h0);
        o.z += s * __low2float(h1);  o.w += s * __high2float(h1);
    }
    *(float4*)(O + ((size_t)b * TF + q) * DIMN + t * 4) = o;
}

extern "C" void kernel_launch(void* const* d_in, const int* in_sizes, int n_in,
                              void* d_out, int out_size)
{
    (void)in_sizes; (void)n_in; (void)out_size;

    const float* eeg   = (const float*)d_in[0];
    const float* fnirs = (const float*)d_in[1];
    const float* Wqe = (const float*)d_in[2];
    const float* bqe = (const float*)d_in[3];
    const float* Wke = (const float*)d_in[4];
    const float* bke = (const float*)d_in[5];
    const float* Wve = (const float*)d_in[6];
    const float* bve = (const float*)d_in[7];
    const float* Wqf = (const float*)d_in[8];
    const float* bqf = (const float*)d_in[9];
    const float* Wkf = (const float*)d_in[10];
    const float* bkf = (const float*)d_in[11];
    const float* Wvf = (const float*)d_in[12];
    const float* bvf = (const float*)d_in[13];

    uint32_t *Ae, *Af, *Wt, *Qe, *Ke, *Ve, *Qf, *Kf, *Vf, *OpartH;
    float *Mb, *Lb;
    cudaGetSymbolAddress((void**)&Ae, g_Ae);
    cudaGetSymbolAddress((void**)&Af, g_Af);
    cudaGetSymbolAddress((void**)&Wt, g_Wt);
    cudaGetSymbolAddress((void**)&Qe, g_Qe);
    cudaGetSymbolAddress((void**)&Ke, g_Ke);
    cudaGetSymbolAddress((void**)&Ve, g_Ve);
    cudaGetSymbolAddress((void**)&Qf, g_Qf);
    cudaGetSymbolAddress((void**)&Kf, g_Kf);
    cudaGetSymbolAddress((void**)&Vf, g_Vf);
    cudaGetSymbolAddress((void**)&OpartH, g_OpartH);
    cudaGetSymbolAddress((void**)&Mb, g_M);
    cudaGetSymbolAddress((void**)&Lb, g_L);

    float* out           = (float*)d_out;
    float* aligned_eeg   = out;                                // [B, TF, D]
    float* aligned_fnirs = out + (size_t)BATCH * TF * DIMN;    // [B, TE, D]

    const int Me = BATCH * TE;
    const int Mf = BATCH * TF;
    const size_t NWW = (size_t)DIMN * DIMW;

    const int ne = Me * DIMN, nf = Mf * DIMN;
    cvt_perm_h<<<(ne / 4 + 255) / 256, 256>>>(eeg,   Ae, ne);
    cvt_perm_h<<<(nf / 4 + 255) / 256, 256>>>(fnirs, Af, nf);
    wt_h_kernel<<<dim3(DIMN / 32, DIMN / 32, 6), dim3(32, 8)>>>(
        Wqe, Wke, Wve, Wqf, Wkf, Wvf, Wt);

    cudaFuncSetAttribute(gemm_mma_kernel,
                         cudaFuncAttributeMaxDynamicSharedMemorySize, GEMM_SMEM_BYTES);

    dim3 blk(256);
    gemm_mma_kernel<<<dim3(12, Me / 128), blk, GEMM_SMEM_BYTES>>>(
        Ae, Wt, bqe, bke, bve, Qe, Ke, Ve);
    gemm_mma_kernel<<<dim3(12, Mf / 128), blk, GEMM_SMEM_BYTES>>>(
        Af, Wt + 3 * NWW, bqf, bkf, bvf, Qf, Kf, Vf);

    cudaFuncSetAttribute((const void*)attn_chunk_kernel<true, true>,
                         cudaFuncAttributeMaxDynamicSharedMemorySize, ATTN_SMEM);
    cudaFuncSetAttribute((const void*)attn_chunk_kernel<false, false>,
                         cudaFuncAttributeMaxDynamicSharedMemorySize, ATTN_SMEM);

    attn_chunk_kernel<true, true><<<dim3(10, BATCH, 1), blk, ATTN_SMEM>>>(
        Qe, Kf, Vf, aligned_fnirs, nullptr, nullptr, nullptr, TE, TF);
    attn_chunk_kernel<false, false><<<dim3(2, BATCH, NCHUNK), blk, ATTN_SMEM>>>(
        Qf, Ke, Ve, nullptr, OpartH, Mb, Lb, TF, TE);
    combine_f2e<<<dim3(TF, BATCH), dim3(128)>>>(OpartH, Mb, Lb, aligned_eeg);
}

// round 17
// speedup vs baseline: 1.2435x; 1.1541x over previous
#include <cuda_runtime.h>
#include <cuda_fp16.h>
#include <cstdint>
#include <math.h>

#define BATCH 128
#define DIMN  512
#define DIMW  256          // row length in half2 words
#define TE    600
#define TF    120
#define NCHUNK 5           // f2e key chunks of 128 covering 600 keys

// ---------------- scratch (device globals; no allocation allowed) ----------------
__device__ uint32_t g_Ae[BATCH * TE * DIMW];   // eeg, half2 words, pair-permuted
__device__ uint32_t g_Af[BATCH * TF * DIMW];   // fnirs, half2 words, pair-permuted
__device__ uint32_t g_Wt[6 * DIMN * DIMW];     // weights [n][k-half2], permuted
__device__ uint32_t g_Qe[BATCH * TE * DIMW];   // Q/K: half2 pair-permuted
__device__ uint32_t g_Ke[BATCH * TE * DIMW];
__device__ uint32_t g_Ve[BATCH * TE * DIMW];   // V: half2 plain
__device__ uint32_t g_Qf[BATCH * TF * DIMW];
__device__ uint32_t g_Kf[BATCH * TF * DIMW];
__device__ uint32_t g_Vf[BATCH * TF * DIMW];
__device__ uint32_t g_OpartH[NCHUNK * BATCH * 128 * DIMW];  // f2e partial O, half2
__device__ float g_M[NCHUNK * BATCH * 128];
__device__ float g_L[NCHUNK * BATCH * 128];

__device__ __forceinline__ uint32_t pack_h2(float lo, float hi) {
    half2 h = __floats2half2_rn(lo, hi);
    return *(uint32_t*)&h;
}

// m16n8k16 fp16 MMA, fp32 accumulate
__device__ __forceinline__ void mma_f16(float* c, const uint32_t* a, const uint32_t* b) {
    asm volatile("mma.sync.aligned.m16n8k16.row.col.f32.f16.f16.f32 "
        "{%0,%1,%2,%3}, {%4,%5,%6,%7}, {%8,%9}, {%0,%1,%2,%3};"
        : "+f"(c[0]), "+f"(c[1]), "+f"(c[2]), "+f"(c[3])
        : "r"(a[0]), "r"(a[1]), "r"(a[2]), "r"(a[3]), "r"(b[0]), "r"(b[1]));
}

__device__ __forceinline__ void cp_async16(uint32_t dst, const void* src) {
    asm volatile("cp.async.cg.shared.global [%0], [%1], 16;" :: "r"(dst), "l"(src));
}
#define CP_COMMIT() asm volatile("cp.async.commit_group;" ::: "memory")
#define CP_WAIT1()  asm volatile("cp.async.wait_group 1;" ::: "memory")

// ------- activation cvt: fp32 -> half2 words, pair-permuted within 8-word groups -
__global__ void cvt_perm_h(const float* __restrict__ src, uint32_t* __restrict__ dst, int n)
{
    const int i = (blockIdx.x * 256 + threadIdx.x) * 4;
    if (i < n) {
        const float4 v = *(const float4*)(src + i);
        const uint32_t w0 = pack_h2(v.x, v.y);
        const uint32_t w1 = pack_h2(v.z, v.w);
        const int p    = i >> 1;
        const int base = p & ~7;
        const int j0   = p & 7;
        const int d0 = (j0 < 4) ? 2 * j0 : 2 * (j0 - 4) + 1;
        const int j1 = j0 + 1;
        const int d1 = (j1 < 4) ? 2 * j1 : 2 * (j1 - 4) + 1;
        dst[base + d0] = w0;
        dst[base + d1] = w1;
    }
}

// ------- weight transform (all 6 matrices in one launch; z selects) --------------
__global__ void wt_h_kernel(const float* __restrict__ W0, const float* __restrict__ W1,
                            const float* __restrict__ W2, const float* __restrict__ W3,
                            const float* __restrict__ W4, const float* __restrict__ W5,
                            uint32_t* __restrict__ Wt)
{
    __shared__ float s[32][33];
    const int k0 = blockIdx.x * 32, n0 = blockIdx.y * 32;
    const int z  = blockIdx.z;
    const float* W = (z == 0) ? W0 : (z == 1) ? W1 : (z == 2) ? W2
                   : (z == 3) ? W3 : (z == 4) ? W4 : W5;
    uint32_t* Wd = Wt + (size_t)z * DIMN * DIMW;
    const int tx = threadIdx.x, ty = threadIdx.y;
#pragma unroll
    for (int r = ty; r < 32; r += 8)
        s[r][tx] = W[(size_t)(k0 + r) * DIMN + n0 + tx];
    __syncthreads();
#pragma unroll
    for (int w = ty; w < 16; w += 8) {
        const uint32_t h = pack_h2(s[2 * w][tx], s[2 * w + 1][tx]);
        const int j  = w & 7;
        const int jp = (j < 4) ? 2 * j : 2 * (j - 4) + 1;
        const int pos = (w & 8) + jp;
        Wd[(size_t)(n0 + tx) * DIMW + k0 / 2 + pos] = h;
    }
}

// =============== fp16 m16n8k16 projection GEMM (128x128, 2 CTA/SM, unrolled) =====
#define GSTAGE_W  4096
#define GB_OFF_W  2048
#define GEMM_SMEM_BYTES (3 * GSTAGE_W * 4)

__global__ __launch_bounds__(256, 2)
void gemm_mma_kernel(const uint32_t* __restrict__ A, const uint32_t* __restrict__ Wt,
                     const float* __restrict__ b0, const float* __restrict__ b1,
                     const float* __restrict__ b2,
                     uint32_t* __restrict__ C0, uint32_t* __restrict__ C1,
                     uint32_t* __restrict__ C2)
{
    extern __shared__ uint32_t smem[];
    const uint32_t sb = (uint32_t)__cvta_generic_to_shared(smem);

    const int tid    = threadIdx.x;
    const int wid    = tid >> 5;
    const int lane   = tid & 31;
    const int warp_m = wid & 1;
    const int warp_n = wid >> 1;
    const int g      = lane >> 2;
    const int t4     = lane & 3;
    const int wsel = blockIdx.x >> 2;
    const int n0   = (blockIdx.x & 3) * 128;
    const int m0   = blockIdx.y * 128;

    const uint32_t* W = Wt + (size_t)wsel * DIMN * DIMW;
    const float* bias = (wsel == 0) ? b0 : (wsel == 1) ? b1 : b2;
    uint32_t* C       = (wsel == 0) ? C0 : (wsel == 1) ? C1 : C2;

    const int sm_ = tid >> 2;
    const int sq  = tid & 3;

    float acc[4][4][4];
#pragma unroll
    for (int mt = 0; mt < 4; mt++)
#pragma unroll
        for (int nt = 0; nt < 4; nt++)
#pragma unroll
            for (int r = 0; r < 4; r++) acc[mt][nt][r] = 0.f;

    auto issue = [&](int c, int s) {
        const uint32_t stA = sb + (uint32_t)(s * GSTAGE_W) * 4;
        const uint32_t stB = sb + (uint32_t)(s * GSTAGE_W + GB_OFF_W) * 4;
#pragma unroll
        for (int i = 0; i < 2; ++i) {
            const int m = sm_ + i * 64;
            const uint32_t dstw = (uint32_t)(m * 16 + ((sq * 4) ^ ((m & 3) << 2)));
            cp_async16(stA + dstw * 4, A + (size_t)(m0 + m) * DIMW + c * 16 + sq * 4);
        }
#pragma unroll
        for (int i = 0; i < 2; ++i) {
            const int nn = sm_ + i * 64;
            const uint32_t dstw = (uint32_t)(nn * 16 + ((sq * 4) ^ ((nn & 3) << 2)));
            cp_async16(stB + dstw * 4, W + (size_t)(n0 + nn) * DIMW + c * 16 + sq * 4);
        }
        CP_COMMIT();
    };

    issue(0, 0);
    issue(1, 1);

    const int sw = (g & 3) << 2;

#pragma unroll
    for (int c = 0; c < 16; ++c) {
        const int s = c % 3;
        CP_WAIT1();
        __syncthreads();
        if (c + 2 < 16) issue(c + 2, (c + 2) % 3);

        const uint32_t* Af = smem + s * GSTAGE_W;
        const uint32_t* Bf = smem + s * GSTAGE_W + GB_OFF_W;
#pragma unroll
        for (int kk = 0; kk < 2; ++kk) {
            const int off = (kk * 8 + 2 * t4) ^ sw;
            uint32_t a[4][4], b[4][2];
#pragma unroll
            for (int mt = 0; mt < 4; ++mt) {
                const int r = warp_m * 64 + mt * 16 + g;
                const uint2 v0 = *(const uint2*)&Af[r * 16 + off];
                const uint2 v1 = *(const uint2*)&Af[(r + 8) * 16 + off];
                a[mt][0] = v0.x; a[mt][1] = v1.x; a[mt][2] = v0.y; a[mt][3] = v1.y;
            }
#pragma unroll
            for (int nt = 0; nt < 4; ++nt) {
                const int n = warp_n * 32 + nt * 8 + g;
                const uint2 vb = *(const uint2*)&Bf[n * 16 + off];
                b[nt][0] = vb.x; b[nt][1] = vb.y;
            }
#pragma unroll
            for (int mt = 0; mt < 4; ++mt)
#pragma unroll
                for (int nt = 0; nt < 4; ++nt)
                    mma_f16(acc[mt][nt], a[mt], b[nt]);
        }
    }

    // epilogue: bias add fp32, pack half2. Q/K (wsel 0,1): pair-permuted; V: plain.
#pragma unroll
    for (int mt = 0; mt < 4; ++mt) {
        const int row = m0 + warp_m * 64 + mt * 16 + g;
#pragma unroll
        for (int nt = 0; nt < 4; ++nt) {
            const int col = n0 + warp_n * 32 + nt * 8 + 2 * t4;
            const float2 bb = *(const float2*)(bias + col);
            const int wplain = n0 / 2 + warp_n * 16 + nt * 4 + t4;
            const int wperm  = n0 / 2 + warp_n * 16 + ((nt & 2) ? 8 : 0) + 2 * t4 + (nt & 1);
            const int dw = (wsel == 2) ? wplain : wperm;
            C[(size_t)row * DIMW + dw] =
                pack_h2(acc[mt][nt][0] + bb.x, acc[mt][nt][1] + bb.y);
            C[(size_t)(row + 8) * DIMW + dw] =
                pack_h2(acc[mt][nt][2] + bb.x, acc[mt][nt][3] + bb.y);
        }
    }
}

// ================= fp16 attention chunk kernel ===================================
#define SS_OFF 0
#define PS_OFF 33792
#define ST_OFF 51200
#define LS_OFF 63488
#define ATTN_SMEM 63744

template <bool E2F, bool FINAL>
__global__ __launch_bounds__(256, 2)
void attn_chunk_kernel(const uint32_t* __restrict__ Q, const uint32_t* __restrict__ K,
                       const uint32_t* __restrict__ V, float* __restrict__ O,
                       uint32_t* __restrict__ OpartH, float* __restrict__ Mb,
                       float* __restrict__ Lb, int Tq, int Tk)
{
    extern __shared__ char smemc[];
    float*    Ss = (float*)(smemc + SS_OFF);
    uint32_t* Ps = (uint32_t*)(smemc + PS_OFF);
    uint32_t* Qs = (uint32_t*)(smemc + ST_OFF);      // [64][16]
    uint32_t* Ks = Qs + 64 * 16;                     // [128][16]
    uint32_t* Vt = Qs;                               // [128][16] (phase-3 alias)
    float*    l_s = (float*)(smemc + LS_OFF);

    const int tid    = threadIdx.x;
    const int wid    = tid >> 5;
    const int lane   = tid & 31;
    const int warp_m = wid & 1;
    const int warp_n = wid >> 1;
    const int g      = lane >> 2;
    const int t4     = lane & 3;
    const int q0     = blockIdx.x * 64;
    const int b      = blockIdx.y;
    const int kchunk = blockIdx.z;
    const float scale = 0.044194173824159216f;
    const float NEG_INF = __int_as_float(0xff800000);
    const int sw = (g & 3) << 2;

    const uint32_t* Qb = Q + (size_t)b * Tq * DIMW;
    const uint32_t* Kb = K + (size_t)b * Tk * DIMW;
    const uint32_t* Vb = V + (size_t)b * Tk * DIMW;

    float acc[2][4][4];
#pragma unroll
    for (int mt = 0; mt < 2; mt++)
#pragma unroll
        for (int nt = 0; nt < 4; nt++)
#pragma unroll
            for (int r = 0; r < 4; r++) acc[mt][nt][r] = 0.f;

#pragma unroll
    for (int ch = 0; ch < 16; ++ch) {
        __syncthreads();
        {
            const int r = tid >> 2, c4 = tid & 3;
            uint4 v = make_uint4(0u, 0u, 0u, 0u);
            if (q0 + r < Tq)
                v = *(const uint4*)(Qb + (size_t)(q0 + r) * DIMW + ch * 16 + c4 * 4);
            *(uint4*)&Qs[r * 16 + ((c4 * 4) ^ ((r & 3) << 2))] = v;
        }
#pragma unroll
        for (int i = 0; i < 2; ++i) {
            const int lin = i * 256 + tid;
            const int r = lin >> 2, c4 = lin & 3;
            const int key = kchunk * 128 + r;
            uint4 v = make_uint4(0u, 0u, 0u, 0u);
            if (key < Tk)
                v = *(const uint4*)(Kb + (size_t)key * DIMW + ch * 16 + c4 * 4);
            *(uint4*)&Ks[r * 16 + ((c4 * 4) ^ ((r & 3) << 2))] = v;
        }
        __syncthreads();
#pragma unroll
        for (int kk = 0; kk < 2; ++kk) {
            const int off = (kk * 8 + 2 * t4) ^ sw;
            uint32_t a[2][4], bb[4][2];
#pragma unroll
            for (int mt = 0; mt < 2; ++mt) {
                const int r = warp_m * 32 + mt * 16 + g;
                const uint2 v0 = *(const uint2*)&Qs[r * 16 + off];
                const uint2 v1 = *(const uint2*)&Qs[(r + 8) * 16 + off];
                a[mt][0] = v0.x; a[mt][1] = v1.x; a[mt][2] = v0.y; a[mt][3] = v1.y;
            }
#pragma unroll
            for (int nt = 0; nt < 4; ++nt) {
                const int n = warp_n * 32 + nt * 8 + g;
                const uint2 vb = *(const uint2*)&Ks[n * 16 + off];
                bb[nt][0] = vb.x; bb[nt][1] = vb.y;
            }
#pragma unroll
            for (int mt = 0; mt < 2; ++mt)
#pragma unroll
                for (int nt = 0; nt < 4; ++nt)
                    mma_f16(acc[mt][nt], a[mt], bb[nt]);
        }
    }
#pragma unroll
    for (int mt = 0; mt < 2; ++mt) {
#pragma unroll
        for (int half = 0; half < 2; ++half) {
            const int row = warp_m * 32 + mt * 16 + half * 8 + g;
            const int q   = q0 + row;
            const int j0g = q / 20;
#pragma unroll
            for (int nt = 0; nt < 4; ++nt) {
                const int colc = warp_n * 32 + nt * 8 + 2 * t4;
                float vout[2];
#pragma unroll
                for (int e = 0; e < 2; ++e) {
                    const int key = kchunk * 128 + colc + e;
                    float val;
                    if (key >= Tk) val = NEG_INF;
                    else {
                        bool valid;
                        if (E2F) valid = (key >= j0g + 20) && (key <= j0g + 80);
                        else { const int gg = key / 20; valid = (q >= gg + 20) && (q <= gg + 80); }
                        val = valid ? acc[mt][nt][half * 2 + e] * scale : -1e9f;
                    }
                    vout[e] = val;
                }
                *(float2*)&Ss[row * 132 + colc] = make_float2(vout[0], vout[1]);
            }
        }
    }
    __syncthreads();

    {
        const int row  = tid >> 2;
        const int part = tid & 3;
        const float* srow = Ss + row * 132;

        float mx = NEG_INF;
#pragma unroll
        for (int i = 0; i < 16; ++i) {
            const float2 s2 = *(const float2*)&srow[2 * (part + 4 * i)];
            mx = fmaxf(mx, fmaxf(s2.x, s2.y));
        }
        mx = fmaxf(mx, __shfl_xor_sync(0xffffffffu, mx, 1));
        mx = fmaxf(mx, __shfl_xor_sync(0xffffffffu, mx, 2));
        float sum = 0.f;
        uint32_t* prow = Ps + row * 68;
#pragma unroll
        for (int i = 0; i < 16; ++i) {
            const int w = part + 4 * i;
            const float2 s2 = *(const float2*)&srow[2 * w];
            const float e0 = __expf(s2.x - mx);
            const float e1 = __expf(s2.y - mx);
            sum += e0 + e1;
            const int j = w & 7;
            const int pw = (w & ~7) + ((j < 4) ? 2 * j : 2 * (j - 4) + 1);
            prow[pw] = pack_h2(e0, e1);
        }
        sum += __shfl_xor_sync(0xffffffffu, sum, 1);
        sum += __shfl_xor_sync(0xffffffffu, sum, 2);
        if (part == 0) {
            l_s[row] = sum;
            if (!FINAL) {
                const int idx = (kchunk * BATCH + b) * 128 + q0 + row;
                Mb[idx] = mx;
                Lb[idx] = sum;
            }
        }
    }
    __syncthreads();

#pragma unroll
    for (int nc = 0; nc < 4; ++nc) {
        float oacc[2][4][4];
#pragma unroll
        for (int mt = 0; mt < 2; mt++)
#pragma unroll
            for (int nt = 0; nt < 4; nt++)
#pragma unroll
                for (int r = 0; r < 4; r++) oacc[mt][nt][r] = 0.f;

#pragma unroll
        for (int ks = 0; ks < 4; ++ks) {
            __syncthreads();
#pragma unroll
            for (int i = 0; i < 4; ++i) {
                const int u  = i * 256 + tid;
                const int kw = (u >> 2) & 15;
                const int wd = (u & 3) | ((u >> 6) << 2);
                const int key0 = kchunk * 128 + ks * 32 + 2 * kw;
                uint32_t w0 = 0u, w1 = 0u;
                if (key0 < Tk)     w0 = Vb[(size_t)key0 * DIMW + nc * 64 + wd];
                if (key0 + 1 < Tk) w1 = Vb[(size_t)(key0 + 1) * DIMW + nc * 64 + wd];
                const uint32_t lo = __byte_perm(w0, w1, 0x5410);
                const uint32_t hi = __byte_perm(w0, w1, 0x7632);
                const int j  = kw & 7;
                const int ps = (kw & 8) + ((j < 4) ? 2 * j : 2 * (j - 4) + 1);
                const int d0 = 2 * wd, d1 = 2 * wd + 1;
                Vt[d0 * 16 + (ps ^ ((d0 & 3) << 2))] = lo;
                Vt[d1 * 16 + (ps ^ ((d1 & 3) << 2))] = hi;
            }
            __syncthreads();
#pragma unroll
            for (int kk = 0; kk < 2; ++kk) {
                const int offv = (kk * 8 + 2 * t4) ^ sw;
                const int offp = ks * 16 + kk * 8 + 2 * t4;
                uint32_t a[2][4], bb[4][2];
#pragma unroll
                for (int mt = 0; mt < 2; ++mt) {
                    const int r = warp_m * 32 + mt * 16 + g;
                    const uint2 v0 = *(const uint2*)&Ps[r * 68 + offp];
                    const uint2 v1 = *(const uint2*)&Ps[(r + 8) * 68 + offp];
                    a[mt][0] = v0.x; a[mt][1] = v1.x; a[mt][2] = v0.y; a[mt][3] = v1.y;
                }
#pragma unroll
                for (int nt = 0; nt < 4; ++nt) {
                    const int n = warp_n * 32 + nt * 8 + g;
                    const uint2 vb = *(const uint2*)&Vt[n * 16 + offv];
                    bb[nt][0] = vb.x; bb[nt][1] = vb.y;
                }
#pragma unroll
                for (int mt = 0; mt < 2; ++mt)
#pragma unroll
                    for (int nt = 0; nt < 4; ++nt)
                        mma_f16(oacc[mt][nt], a[mt], bb[nt]);
            }
        }
#pragma unroll
        for (int mt = 0; mt < 2; ++mt) {
#pragma unroll
            for (int half = 0; half < 2; ++half) {
                const int row = warp_m * 32 + mt * 16 + half * 8 + g;
                const int q   = q0 + row;
#pragma unroll
                for (int nt = 0; nt < 4; ++nt) {
                    const int col = nc * 128 + warp_n * 32 + nt * 8 + 2 * t4;
                    const float v0 = oacc[mt][nt][half * 2 + 0];
                    const float v1 = oacc[mt][nt][half * 2 + 1];
                    if (FINAL) {
                        if (q < Tq) {
                            const float inv = 1.f / l_s[row];
                            *(float2*)(O + ((size_t)b * Tq + q) * DIMN + col) =
                                make_float2(v0 * inv, v1 * inv);
                        }
                    } else {
                        OpartH[(((size_t)kchunk * BATCH + b) * 128 + q) * DIMW + col / 2] =
                            pack_h2(v0, v1);
                    }
                }
            }
        }
    }
}

// ----------------- f2e combine: merge 5 fp16 chunk partials per row --------------
__global__ void combine_f2e(const uint32_t* __restrict__ OpartH,
                            const float* __restrict__ Mb, const float* __restrict__ Lb,
                            float* __restrict__ O)
{
    const int q = blockIdx.x;
    const int b = blockIdx.y;
    const int t = threadIdx.x;
    float m[NCHUNK], w[NCHUNK];
    float M = __int_as_float(0xff800000);
#pragma unroll
    for (int c = 0; c < NCHUNK; ++c) {
        m[c] = Mb[(c * BATCH + b) * 128 + q];
        M = fmaxf(M, m[c]);
    }
    float den = 0.f;
#pragma unroll
    for (int c = 0; c < NCHUNK; ++c) {
        w[c] = __expf(m[c] - M);
        den += w[c] * Lb[(c * BATCH + b) * 128 + q];
    }
    const float inv = 1.f / den;
    float4 o = make_float4(0.f, 0.f, 0.f, 0.f);
#pragma unroll
    for (int c = 0; c < NCHUNK; ++c) {
        const uint2 p2 = *(const uint2*)(OpartH + (((size_t)c * BATCH + b) * 128 + q) * DIMW + t * 2);
        const half2 h0 = *(const half2*)&p2.x;
        const half2 h1 = *(const half2*)&p2.y;
        const float s = w[c] * inv;
        o.x += s * __low2float(h0);  o.y += s * __high2float(h0);
        o.z += s * __low2float(h1);  o.w += s * __high2float(h1);
    }
    *(float4*)(O + ((size_t)b * TF + q) * DIMN + t * 4) = o;
}

extern "C" void kernel_launch(void* const* d_in, const int* in_sizes, int n_in,
                              void* d_out, int out_size)
{
    (void)in_sizes; (void)n_in; (void)out_size;

    const float* eeg   = (const float*)d_in[0];
    const float* fnirs = (const float*)d_in[1];
    const float* Wqe = (const float*)d_in[2];
    const float* bqe = (const float*)d_in[3];
    const float* Wke = (const float*)d_in[4];
    const float* bke = (const float*)d_in[5];
    const float* Wve = (const float*)d_in[6];
    const float* bve = (const float*)d_in[7];
    const float* Wqf = (const float*)d_in[8];
    const float* bqf = (const float*)d_in[9];
    const float* Wkf = (const float*)d_in[10];
    const float* bkf = (const float*)d_in[11];
    const float* Wvf = (const float*)d_in[12];
    const float* bvf = (const float*)d_in[13];

    uint32_t *Ae, *Af, *Wt, *Qe, *Ke, *Ve, *Qf, *Kf, *Vf, *OpartH;
    float *Mb, *Lb;
    cudaGetSymbolAddress((void**)&Ae, g_Ae);
    cudaGetSymbolAddress((void**)&Af, g_Af);
    cudaGetSymbolAddress((void**)&Wt, g_Wt);
    cudaGetSymbolAddress((void**)&Qe, g_Qe);
    cudaGetSymbolAddress((void**)&Ke, g_Ke);
    cudaGetSymbolAddress((void**)&Ve, g_Ve);
    cudaGetSymbolAddress((void**)&Qf, g_Qf);
    cudaGetSymbolAddress((void**)&Kf, g_Kf);
    cudaGetSymbolAddress((void**)&Vf, g_Vf);
    cudaGetSymbolAddress((void**)&OpartH, g_OpartH);
    cudaGetSymbolAddress((void**)&Mb, g_M);
    cudaGetSymbolAddress((void**)&Lb, g_L);

    float* out           = (float*)d_out;
    float* aligned_eeg   = out;                                // [B, TF, D]
    float* aligned_fnirs = out + (size_t)BATCH * TF * DIMN;    // [B, TE, D]

    const int Me = BATCH * TE;
    const int Mf = BATCH * TF;
    const size_t NWW = (size_t)DIMN * DIMW;

    const int ne = Me * DIMN, nf = Mf * DIMN;
    cvt_perm_h<<<(ne / 4 + 255) / 256, 256>>>(eeg,   Ae, ne);
    cvt_perm_h<<<(nf / 4 + 255) / 256, 256>>>(fnirs, Af, nf);
    wt_h_kernel<<<dim3(DIMN / 32, DIMN / 32, 6), dim3(32, 8)>>>(
        Wqe, Wke, Wve, Wqf, Wkf, Wvf, Wt);

    cudaFuncSetAttribute(gemm_mma_kernel,
                         cudaFuncAttributeMaxDynamicSharedMemorySize, GEMM_SMEM_BYTES);

    dim3 blk(256);
    gemm_mma_kernel<<<dim3(12, Me / 128), blk, GEMM_SMEM_BYTES>>>(
        Ae, Wt, bqe, bke, bve, Qe, Ke, Ve);
    gemm_mma_kernel<<<dim3(12, Mf / 128), blk, GEMM_SMEM_BYTES>>>(
        Af, Wt + 3 * NWW, bqf, bkf, bvf, Qf, Kf, Vf);

    cudaFuncSetAttribute((const void*)attn_chunk_kernel<true, true>,
                         cudaFuncAttributeMaxDynamicSharedMemorySize, ATTN_SMEM);
    cudaFuncSetAttribute((const void*)attn_chunk_kernel<false, false>,
                         cudaFuncAttributeMaxDynamicSharedMemorySize, ATTN_SMEM);

    attn_chunk_kernel<true, true><<<dim3(10, BATCH, 1), blk, ATTN_SMEM>>>(
        Qe, Kf, Vf, aligned_fnirs, nullptr, nullptr, nullptr, TE, TF);
    attn_chunk_kernel<false, false><<<dim3(2, BATCH, NCHUNK), blk, ATTN_SMEM>>>(
        Qf, Ke, Ve, nullptr, OpartH, Mb, Lb, TF, TE);
    combine_f2e<<<dim3(TF, BATCH), dim3(128)>>>(OpartH, Mb, Lb, aligned_eeg);
}